// round 12
// baseline (speedup 1.0000x reference)
#include <cuda_runtime.h>
#include <cstdint>

// YoloLoss: y (16384,7,7,30) f32, gt same -> scalar f32.
// HBM-bound reduction: 192.7 MB read, 4 B written. Single fused kernel:
//  - smem-staged tiles, coalesced float2 global loads, conflict-free padded LDS
//  - last-block-done in-kernel finalize (no second launch)

#define LAMBDA_COORD 5.0f
#define LAMBDA_NOOBJ 0.5f

static constexpr int B_SZ  = 16384;
static constexpr int NCELL = 16384 * 7 * 7;       // 802816
static constexpr int TPB   = 128;                 // threads per block
static constexpr int CPT   = 128;                 // cells per tile (== TPB)
static constexpr int TILES = 8;                   // tiles per block
static constexpr int NBLK  = NCELL / (CPT * TILES); // 784, exact
static constexpr int PAD   = 31;                  // padded floats per cell (gcd(31,32)=1)

__device__ double       g_partials[NBLK];
__device__ unsigned int g_count = 0;              // self-resetting ticket

__device__ __forceinline__ float iou_f(float x1, float y1, float w1, float h1,
                                       float x2, float y2, float w2, float h2) {
    float xl = fmaxf(x1 - 0.5f * w1, x2 - 0.5f * w2);
    float yt = fmaxf(y1 - 0.5f * h1, y2 - 0.5f * h2);
    float xr = fminf(x1 + 0.5f * w1, x2 + 0.5f * w2);
    float yb = fminf(y1 + 0.5f * h1, y2 + 0.5f * h2);
    bool valid = (xr >= xl) && (yb >= yt);
    float inter = (xr - xl) * (yb - yt);
    float uni = w1 * h1 + w2 * h2 - inter;
    float safe = (uni == 0.0f) ? 1.0f : uni;
    return valid ? (inter / safe) : 0.0f;
}

// Block-wide deterministic double reduction (TPB = 128 -> 4 warps).
__device__ __forceinline__ double block_reduce(double v, double* warp_sums,
                                               int lane, int wid) {
#pragma unroll
    for (int off = 16; off > 0; off >>= 1)
        v += __shfl_down_sync(0xFFFFFFFFu, v, off);
    if (lane == 0) warp_sums[wid] = v;
    __syncthreads();
    double s = 0.0;
    if (wid == 0) {
        s = (lane < TPB / 32) ? warp_sums[lane] : 0.0;
#pragma unroll
        for (int off = 2; off > 0; off >>= 1)
            s += __shfl_down_sync(0xFFFFFFFFu, s, off);
    }
    return s;   // valid in (wid==0, lane==0)
}

__global__ __launch_bounds__(TPB) void yolo_fused_kernel(
    const float* __restrict__ y, const float* __restrict__ gt,
    float* __restrict__ out)
{
    __shared__ float sy[CPT * PAD];        // staged pred tile (padded)
    __shared__ float sg[CPT * PAD];        // staged target tile (padded)
    __shared__ double warp_sums[TPB / 32];
    __shared__ int    is_last;

    const int tid  = threadIdx.x;
    const int lane = tid & 31;
    const int wid  = tid >> 5;

    double acc = 0.0;

#pragma unroll 1
    for (int tl = 0; tl < TILES; ++tl) {
        const size_t cellbase = ((size_t)blockIdx.x * TILES + tl) * CPT;
        const float2* __restrict__ yp =
            reinterpret_cast<const float2*>(y)  + cellbase * 15;
        const float2* __restrict__ gp =
            reinterpret_cast<const float2*>(gt) + cellbase * 15;

        __syncthreads();   // previous tile's smem reads complete before overwrite

        // Perfectly coalesced float2 loads, scatter into padded smem layout.
#pragma unroll
        for (int k = 0; k < 15; ++k) {
            float2 a = yp[k * CPT + tid];
            float2 b = gp[k * CPT + tid];
            int e0 = 2 * (k * CPT + tid);
            int c0 = e0 / 30, f0 = e0 - c0 * 30;
            int e1 = e0 + 1;
            int c1 = e1 / 30, f1 = e1 - c1 * 30;
            sy[c0 * PAD + f0] = a.x;  sy[c1 * PAD + f1] = a.y;
            sg[c0 * PAD + f0] = b.x;  sg[c1 * PAD + f1] = b.y;
        }
        __syncthreads();

        // Each thread computes its cell from smem (stride-31 -> conflict-free).
        const float* __restrict__ p = &sy[tid * PAD];
        const float* __restrict__ t = &sg[tid * PAD];

        const float obj   = (t[4] > 0.0f)  ? 1.0f : 0.0f;
        const float noobj = (t[4] == 0.0f) ? 1.0f : 0.0f;   // NOT 1-obj (matches ref)

        float class_loss = 0.0f;
#pragma unroll
        for (int d = 10; d < 30; d++) {
            float df = t[d] - p[d];
            class_loss = fmaf(df, df, class_loss);
        }
        class_loss *= obj;

        float dconf = t[4] - p[4];
        float conf_noobj = noobj * dconf * dconf;

        float iou1 = iou_f(t[0], t[1], t[2], t[3], p[0], p[1], p[2], p[3]);
        float iou2 = iou_f(t[0], t[1], t[2], t[3], p[5], p[6], p[7], p[8]);
        float resp1 = (iou1 > iou2) ? 1.0f : 0.0f;
        float m1 = obj * resp1;
        float m2 = obj * (1.0f - resp1);

        float e1v = iou1 - p[4];
        float e2v = iou2 - p[9];
        float conf_obj = m1 * e1v * e1v + m2 * e2v * e2v;

        float dx1 = t[0] - p[0], dy1 = t[1] - p[1];
        float dx2 = t[0] - p[5], dy2 = t[1] - p[6];
        float xy = m1 * (dx1 * dx1 + dy1 * dy1) + m2 * (dx2 * dx2 + dy2 * dy2);

        float dw1 = t[2] - p[2], dh1 = t[3] - p[3];
        float dw2 = t[2] - p[7], dh2 = t[3] - p[8];
        float wh = m1 * (dw1 * dw1 + dh1 * dh1) + m2 * (dw2 * dw2 + dh2 * dh2);

        float cell = LAMBDA_COORD * (xy + wh) + conf_obj
                   + LAMBDA_NOOBJ * conf_noobj + class_loss;
        acc += (double)cell;
    }

    // ---- per-block partial ----
    double bsum = block_reduce(acc, warp_sums, lane, wid);
    if (tid == 0) {
        g_partials[blockIdx.x] = bsum;
        __threadfence();
        unsigned old = atomicAdd(&g_count, 1u);
        is_last = (old == (unsigned)(NBLK - 1)) ? 1 : 0;
    }
    __syncthreads();

    // ---- last block: deterministic finalize, then reset ticket ----
    if (is_last) {
        double s = 0.0;
        for (int i = tid; i < NBLK; i += TPB)
            s += g_partials[i];
        double total = block_reduce(s, warp_sums, lane, wid);
        if (tid == 0) {
            out[0] = (float)(total / (double)B_SZ);
            g_count = 0;    // ready for next graph replay
        }
    }
}

extern "C" void kernel_launch(void* const* d_in, const int* in_sizes, int n_in,
                              void* d_out, int out_size)
{
    const float* y  = (const float*)d_in[0];
    const float* gt = (const float*)d_in[1];
    float* out = (float*)d_out;

    yolo_fused_kernel<<<NBLK, TPB>>>(y, gt, out);
}

// round 14
// speedup vs baseline: 1.0936x; 1.0936x over previous
#include <cuda_runtime.h>
#include <cstdint>

// YoloLoss: y (16384,7,7,30) f32, gt same -> scalar f32.
// HBM-bound streaming reduction: 192.7 MB read, 4 B written.
// Single fused kernel: cp.async double-buffered smem tiles (zero register
// staging, load/compute overlap), linear smem layout (2-way LDS conflicts,
// non-binding), last-block in-kernel finalize.

#define LAMBDA_COORD 5.0f
#define LAMBDA_NOOBJ 0.5f

static constexpr int B_SZ   = 16384;
static constexpr int NCELL  = 16384 * 7 * 7;     // 802816
static constexpr int TPB    = 128;
static constexpr int CPT    = 128;               // cells per tile (== TPB)
static constexpr int NTILES = NCELL / CPT;       // 6272
static constexpr int NBLK   = 392;               // 6272 / 392 = 16 tiles/block, single wave
static constexpr int TPBLK  = NTILES / NBLK;     // 16
static constexpr int TILE_FLOATS = CPT * 30;     // 3840 floats per array per tile
static constexpr int TILE_CHUNKS = TILE_FLOATS / 4;  // 960 x 16B cp.async chunks
static constexpr int SMEM_BYTES  = 2 /*stages*/ * 2 /*arrays*/ * TILE_FLOATS * 4; // 61440

__device__ double       g_partials[NBLK];
__device__ unsigned int g_count = 0;             // self-resetting ticket

__device__ __forceinline__ void cp_async16(uint32_t smem_addr, const void* gptr) {
    asm volatile("cp.async.cg.shared.global [%0], [%1], 16;\n"
                 :: "r"(smem_addr), "l"(gptr));
}
__device__ __forceinline__ void cp_commit() {
    asm volatile("cp.async.commit_group;\n" ::: "memory");
}
template <int N>
__device__ __forceinline__ void cp_wait() {
    asm volatile("cp.async.wait_group %0;\n" :: "n"(N) : "memory");
}

__device__ __forceinline__ float iou_f(float x1, float y1, float w1, float h1,
                                       float x2, float y2, float w2, float h2) {
    float xl = fmaxf(x1 - 0.5f * w1, x2 - 0.5f * w2);
    float yt = fmaxf(y1 - 0.5f * h1, y2 - 0.5f * h2);
    float xr = fminf(x1 + 0.5f * w1, x2 + 0.5f * w2);
    float yb = fminf(y1 + 0.5f * h1, y2 + 0.5f * h2);
    bool valid = (xr >= xl) && (yb >= yt);
    float inter = (xr - xl) * (yb - yt);
    float uni = w1 * h1 + w2 * h2 - inter;
    float safe = (uni == 0.0f) ? 1.0f : uni;
    return valid ? (inter / safe) : 0.0f;
}

// Block-wide deterministic double reduction (TPB = 128 -> 4 warps).
__device__ __forceinline__ double block_reduce(double v, double* warp_sums,
                                               int lane, int wid) {
#pragma unroll
    for (int off = 16; off > 0; off >>= 1)
        v += __shfl_down_sync(0xFFFFFFFFu, v, off);
    if (lane == 0) warp_sums[wid] = v;
    __syncthreads();
    double s = 0.0;
    if (wid == 0) {
        s = (lane < TPB / 32) ? warp_sums[lane] : 0.0;
#pragma unroll
        for (int off = 2; off > 0; off >>= 1)
            s += __shfl_down_sync(0xFFFFFFFFu, s, off);
    }
    return s;   // valid in (wid==0, lane==0)
}

extern __shared__ float smem[];   // [stage][array(y,gt)][TILE_FLOATS]

__global__ __launch_bounds__(TPB) void yolo_fused_kernel(
    const float* __restrict__ y, const float* __restrict__ gt,
    float* __restrict__ out)
{
    __shared__ double warp_sums[TPB / 32];
    __shared__ int    is_last;

    const int tid  = threadIdx.x;
    const int lane = tid & 31;
    const int wid  = tid >> 5;

    const int tile0 = blockIdx.x * TPBLK;   // contiguous tile range per block

    const uint32_t smem_base = (uint32_t)__cvta_generic_to_shared(smem);

    // Issue copies for (tile) into (stage): y -> slot 2*stage, gt -> slot 2*stage+1
    auto prefetch = [&](int tile, int stage) {
        const size_t gbase = (size_t)(tile0 + tile) * TILE_FLOATS;
        const uint32_t sy = smem_base + (uint32_t)((2 * stage + 0) * TILE_FLOATS * 4);
        const uint32_t sg = smem_base + (uint32_t)((2 * stage + 1) * TILE_FLOATS * 4);
#pragma unroll 1
        for (int i = tid; i < TILE_CHUNKS; i += TPB) {
            cp_async16(sy + (uint32_t)i * 16, y  + gbase + (size_t)i * 4);
            cp_async16(sg + (uint32_t)i * 16, gt + gbase + (size_t)i * 4);
        }
        cp_commit();
    };

    double acc = 0.0;

    prefetch(0, 0);

#pragma unroll 1
    for (int tl = 0; tl < TPBLK; ++tl) {
        const int stage = tl & 1;
        if (tl + 1 < TPBLK) {
            prefetch(tl + 1, (tl + 1) & 1);
            cp_wait<1>();       // current tile's group complete
        } else {
            cp_wait<0>();
        }
        __syncthreads();        // all threads' copies of this tile visible

        const float* __restrict__ p = &smem[(2 * stage + 0) * TILE_FLOATS + tid * 30];
        const float* __restrict__ t = &smem[(2 * stage + 1) * TILE_FLOATS + tid * 30];

        const float obj   = (t[4] > 0.0f)  ? 1.0f : 0.0f;
        const float noobj = (t[4] == 0.0f) ? 1.0f : 0.0f;   // NOT 1-obj (matches ref)

        float class_loss = 0.0f;
#pragma unroll
        for (int d = 10; d < 30; d++) {
            float df = t[d] - p[d];
            class_loss = fmaf(df, df, class_loss);
        }
        class_loss *= obj;

        float dconf = t[4] - p[4];
        float conf_noobj = noobj * dconf * dconf;

        float iou1 = iou_f(t[0], t[1], t[2], t[3], p[0], p[1], p[2], p[3]);
        float iou2 = iou_f(t[0], t[1], t[2], t[3], p[5], p[6], p[7], p[8]);
        float resp1 = (iou1 > iou2) ? 1.0f : 0.0f;
        float m1 = obj * resp1;
        float m2 = obj * (1.0f - resp1);

        float e1v = iou1 - p[4];
        float e2v = iou2 - p[9];
        float conf_obj = m1 * e1v * e1v + m2 * e2v * e2v;

        float dx1 = t[0] - p[0], dy1 = t[1] - p[1];
        float dx2 = t[0] - p[5], dy2 = t[1] - p[6];
        float xy = m1 * (dx1 * dx1 + dy1 * dy1) + m2 * (dx2 * dx2 + dy2 * dy2);

        float dw1 = t[2] - p[2], dh1 = t[3] - p[3];
        float dw2 = t[2] - p[7], dh2 = t[3] - p[8];
        float wh = m1 * (dw1 * dw1 + dh1 * dh1) + m2 * (dw2 * dw2 + dh2 * dh2);

        float cell = LAMBDA_COORD * (xy + wh) + conf_obj
                   + LAMBDA_NOOBJ * conf_noobj + class_loss;
        acc += (double)cell;

        __syncthreads();        // everyone done reading this stage before tl+2 overwrites it
    }

    // ---- per-block partial ----
    double bsum = block_reduce(acc, warp_sums, lane, wid);
    if (tid == 0) {
        g_partials[blockIdx.x] = bsum;
        __threadfence();
        unsigned old = atomicAdd(&g_count, 1u);
        is_last = (old == (unsigned)(NBLK - 1)) ? 1 : 0;
    }
    __syncthreads();

    // ---- last block: deterministic finalize, then reset ticket ----
    if (is_last) {
        double s = 0.0;
        for (int i = tid; i < NBLK; i += TPB)
            s += g_partials[i];
        double total = block_reduce(s, warp_sums, lane, wid);
        if (tid == 0) {
            out[0] = (float)(total / (double)B_SZ);
            g_count = 0;    // ready for next graph replay
        }
    }
}

extern "C" void kernel_launch(void* const* d_in, const int* in_sizes, int n_in,
                              void* d_out, int out_size)
{
    const float* y  = (const float*)d_in[0];
    const float* gt = (const float*)d_in[1];
    float* out = (float*)d_out;

    cudaFuncSetAttribute(yolo_fused_kernel,
                         cudaFuncAttributeMaxDynamicSharedMemorySize, SMEM_BYTES);
    yolo_fused_kernel<<<NBLK, TPB, SMEM_BYTES>>>(y, gt, out);
}

// round 15
// speedup vs baseline: 1.1535x; 1.0548x over previous
#include <cuda_runtime.h>
#include <cstdint>

// YoloLoss: y (16384,7,7,30) f32, gt same -> scalar f32.
// HBM-bound streaming reduction: 192.7 MB read, 4 B written.
// Single fused kernel: 3-stage cp.async pipeline (prefetch 2 tiles ahead),
// grid-stride tiles over a persistent 296-block single wave (2 blocks/SM),
// float2 smem reads, last-block in-kernel finalize.

#define LAMBDA_COORD 5.0f
#define LAMBDA_NOOBJ 0.5f

static constexpr int B_SZ   = 16384;
static constexpr int NCELL  = 16384 * 7 * 7;     // 802816
static constexpr int TPB    = 128;
static constexpr int CPT    = 128;               // cells per tile (== TPB)
static constexpr int NTILES = NCELL / CPT;       // 6272
static constexpr int NBLK   = 296;               // 2 blocks/SM * 148 SMs, single wave
static constexpr int STAGES = 3;
static constexpr int TILE_FLOATS = CPT * 30;     // 3840 floats per array per tile
static constexpr int TILE_CHUNKS = TILE_FLOATS / 4;  // 960 x 16B cp.async chunks
static constexpr int SMEM_BYTES  = STAGES * 2 * TILE_FLOATS * 4;  // 92160

__device__ double       g_partials[NBLK];
__device__ unsigned int g_count = 0;             // self-resetting ticket

__device__ __forceinline__ void cp_async16(uint32_t smem_addr, const void* gptr) {
    asm volatile("cp.async.cg.shared.global [%0], [%1], 16;\n"
                 :: "r"(smem_addr), "l"(gptr));
}
__device__ __forceinline__ void cp_commit() {
    asm volatile("cp.async.commit_group;\n" ::: "memory");
}
template <int N>
__device__ __forceinline__ void cp_wait() {
    asm volatile("cp.async.wait_group %0;\n" :: "n"(N) : "memory");
}

__device__ __forceinline__ float iou_f(float x1, float y1, float w1, float h1,
                                       float x2, float y2, float w2, float h2) {
    float xl = fmaxf(x1 - 0.5f * w1, x2 - 0.5f * w2);
    float yt = fmaxf(y1 - 0.5f * h1, y2 - 0.5f * h2);
    float xr = fminf(x1 + 0.5f * w1, x2 + 0.5f * w2);
    float yb = fminf(y1 + 0.5f * h1, y2 + 0.5f * h2);
    bool valid = (xr >= xl) && (yb >= yt);
    float inter = (xr - xl) * (yb - yt);
    float uni = w1 * h1 + w2 * h2 - inter;
    float safe = (uni == 0.0f) ? 1.0f : uni;
    return valid ? (inter / safe) : 0.0f;
}

// Block-wide deterministic double reduction (TPB = 128 -> 4 warps).
__device__ __forceinline__ double block_reduce(double v, double* warp_sums,
                                               int lane, int wid) {
#pragma unroll
    for (int off = 16; off > 0; off >>= 1)
        v += __shfl_down_sync(0xFFFFFFFFu, v, off);
    if (lane == 0) warp_sums[wid] = v;
    __syncthreads();
    double s = 0.0;
    if (wid == 0) {
        s = (lane < TPB / 32) ? warp_sums[lane] : 0.0;
#pragma unroll
        for (int off = 2; off > 0; off >>= 1)
            s += __shfl_down_sync(0xFFFFFFFFu, s, off);
    }
    return s;   // valid in (wid==0, lane==0)
}

extern __shared__ float smem[];   // [stage][array(y,gt)][TILE_FLOATS]

__global__ __launch_bounds__(TPB) void yolo_fused_kernel(
    const float* __restrict__ y, const float* __restrict__ gt,
    float* __restrict__ out)
{
    __shared__ double warp_sums[TPB / 32];
    __shared__ int    is_last;

    const int tid  = threadIdx.x;
    const int lane = tid & 31;
    const int wid  = tid >> 5;

    // grid-stride tile list: tile(k) = blockIdx.x + k*NBLK
    const int nt = (NTILES - blockIdx.x + NBLK - 1) / NBLK;   // 21 or 22

    const uint32_t smem_base = (uint32_t)__cvta_generic_to_shared(smem);

    auto prefetch = [&](int k) {   // k-th tile of this block -> stage k%STAGES
        const int tile = blockIdx.x + k * NBLK;
        const int stage = k % STAGES;
        const size_t gbase = (size_t)tile * TILE_FLOATS;
        const uint32_t sy = smem_base + (uint32_t)((2 * stage + 0) * TILE_FLOATS * 4);
        const uint32_t sg = smem_base + (uint32_t)((2 * stage + 1) * TILE_FLOATS * 4);
#pragma unroll 1
        for (int i = tid; i < TILE_CHUNKS; i += TPB) {
            cp_async16(sy + (uint32_t)i * 16, y  + gbase + (size_t)i * 4);
            cp_async16(sg + (uint32_t)i * 16, gt + gbase + (size_t)i * 4);
        }
        cp_commit();
    };

    double acc = 0.0;

    prefetch(0);            // group 0
    if (nt > 1) prefetch(1); else cp_commit();   // group 1

#pragma unroll 1
    for (int k = 0; k < nt; ++k) {
        __syncthreads();    // compute(k-1) done -> buffer (k+2)%3 is free
        if (k + 2 < nt) prefetch(k + 2); else cp_commit();   // group k+2
        cp_wait<2>();       // groups complete in order -> group k done
        __syncthreads();    // all threads' copies of tile k visible

        const int stage = k % STAGES;
        const float2* __restrict__ p2 = reinterpret_cast<const float2*>(
            &smem[(2 * stage + 0) * TILE_FLOATS + tid * 30]);
        const float2* __restrict__ t2 = reinterpret_cast<const float2*>(
            &smem[(2 * stage + 1) * TILE_FLOATS + tid * 30]);

        float p[30], t[30];
#pragma unroll
        for (int i = 0; i < 15; i++) {
            float2 a = p2[i]; p[2*i] = a.x; p[2*i+1] = a.y;
            float2 b = t2[i]; t[2*i] = b.x; t[2*i+1] = b.y;
        }

        const float obj   = (t[4] > 0.0f)  ? 1.0f : 0.0f;
        const float noobj = (t[4] == 0.0f) ? 1.0f : 0.0f;   // NOT 1-obj (matches ref)

        float class_loss = 0.0f;
#pragma unroll
        for (int d = 10; d < 30; d++) {
            float df = t[d] - p[d];
            class_loss = fmaf(df, df, class_loss);
        }
        class_loss *= obj;

        float dconf = t[4] - p[4];
        float conf_noobj = noobj * dconf * dconf;

        float iou1 = iou_f(t[0], t[1], t[2], t[3], p[0], p[1], p[2], p[3]);
        float iou2 = iou_f(t[0], t[1], t[2], t[3], p[5], p[6], p[7], p[8]);
        float resp1 = (iou1 > iou2) ? 1.0f : 0.0f;
        float m1 = obj * resp1;
        float m2 = obj * (1.0f - resp1);

        float e1v = iou1 - p[4];
        float e2v = iou2 - p[9];
        float conf_obj = m1 * e1v * e1v + m2 * e2v * e2v;

        float dx1 = t[0] - p[0], dy1 = t[1] - p[1];
        float dx2 = t[0] - p[5], dy2 = t[1] - p[6];
        float xy = m1 * (dx1 * dx1 + dy1 * dy1) + m2 * (dx2 * dx2 + dy2 * dy2);

        float dw1 = t[2] - p[2], dh1 = t[3] - p[3];
        float dw2 = t[2] - p[7], dh2 = t[3] - p[8];
        float wh = m1 * (dw1 * dw1 + dh1 * dh1) + m2 * (dw2 * dw2 + dh2 * dh2);

        float cell = LAMBDA_COORD * (xy + wh) + conf_obj
                   + LAMBDA_NOOBJ * conf_noobj + class_loss;
        acc += (double)cell;
    }

    // ---- per-block partial ----
    double bsum = block_reduce(acc, warp_sums, lane, wid);
    if (tid == 0) {
        g_partials[blockIdx.x] = bsum;
        __threadfence();
        unsigned old = atomicAdd(&g_count, 1u);
        is_last = (old == (unsigned)(NBLK - 1)) ? 1 : 0;
    }
    __syncthreads();

    // ---- last block: deterministic finalize, then reset ticket ----
    if (is_last) {
        double s = 0.0;
        for (int i = tid; i < NBLK; i += TPB)
            s += g_partials[i];
        double total = block_reduce(s, warp_sums, lane, wid);
        if (tid == 0) {
            out[0] = (float)(total / (double)B_SZ);
            g_count = 0;    // ready for next graph replay
        }
    }
}

extern "C" void kernel_launch(void* const* d_in, const int* in_sizes, int n_in,
                              void* d_out, int out_size)
{
    const float* y  = (const float*)d_in[0];
    const float* gt = (const float*)d_in[1];
    float* out = (float*)d_out;

    cudaFuncSetAttribute(yolo_fused_kernel,
                         cudaFuncAttributeMaxDynamicSharedMemorySize, SMEM_BYTES);
    yolo_fused_kernel<<<NBLK, TPB, SMEM_BYTES>>>(y, gt, out);
}